// round 5
// baseline (speedup 1.0000x reference)
#include <cuda_runtime.h>
#include <math.h>

// Problem constants
#define T_TOK 4096
#define HID   1024
#define INTER 4096
#define NEXP  8
#define NSLOT 12288          // T*K routed + T shared
#define SHARED_OFF 8192      // T*K
#define MAX_TILES 224        // >= sum ceil(n_e/64) (<=136) + 64 shared tiles

#define BM 64
#define BN 64
#define BK 16

// ---- device-global scratch (no allocations allowed) ----
__device__ float g_act[(size_t)NSLOT * INTER];   // swiglu activations
__device__ float g_y[(size_t)NSLOT * HID];       // per-slot weighted down-proj output
__device__ int   g_perm_token[NSLOT];
__device__ float g_perm_weight[NSLOT];
__device__ int   g_slot_of[T_TOK * 3];           // t -> {routed0, routed1, shared} slots
__device__ int   g_counts[NEXP];
__device__ int   g_offsets[NEXP + 1];
__device__ int   g_cursor[NEXP];
__device__ float g_zloss[T_TOK];
__device__ int   g_tok_e[T_TOK * 2];
__device__ float g_tok_w[T_TOK * 2];
__device__ int   g_tile_expert[MAX_TILES];
__device__ int   g_tile_row0[MAX_TILES];
__device__ int   g_tile_rows[MAX_TILES];
__device__ int   g_num_tiles;

// ---------------------------------------------------------------------------
__global__ void k_zero() {
    int i = threadIdx.x;
    if (i < NEXP) { g_counts[i] = 0; g_cursor[i] = 0; }
}

// ---------------------------------------------------------------------------
// Router: one warp per token. logits = x @ router_w^T, softmax, top-2,
// z-loss, expert counts.
__global__ __launch_bounds__(256)
void k_router(const float* __restrict__ x, const float* __restrict__ rw) {
    __shared__ float s_rw[NEXP * HID];
    for (int i = threadIdx.x; i < NEXP * HID; i += 256) s_rw[i] = rw[i];
    __syncthreads();

    int warp = threadIdx.x >> 5, lane = threadIdx.x & 31;
    int t = blockIdx.x * 8 + warp;
    const float* xr = x + (size_t)t * HID;

    float acc[NEXP];
    #pragma unroll
    for (int e = 0; e < NEXP; e++) acc[e] = 0.f;
    for (int k = lane; k < HID; k += 32) {
        float xv = xr[k];
        #pragma unroll
        for (int e = 0; e < NEXP; e++) acc[e] += xv * s_rw[e * HID + k];
    }
    #pragma unroll
    for (int e = 0; e < NEXP; e++) {
        #pragma unroll
        for (int o = 16; o > 0; o >>= 1)
            acc[e] += __shfl_xor_sync(0xffffffffu, acc[e], o);
    }
    if (lane == 0) {
        float m = acc[0];
        #pragma unroll
        for (int e = 1; e < NEXP; e++) m = fmaxf(m, acc[e]);
        float p[NEXP], s = 0.f, z = 0.f;
        #pragma unroll
        for (int e = 0; e < NEXP; e++) {
            z += acc[e] * acc[e];
            p[e] = expf(acc[e] - m);
            s += p[e];
        }
        float inv = 1.f / s;
        #pragma unroll
        for (int e = 0; e < NEXP; e++) p[e] *= inv;
        // top-2, strict > gives jax top_k tie-break (lower index first)
        int e0 = 0;
        #pragma unroll
        for (int e = 1; e < NEXP; e++) if (p[e] > p[e0]) e0 = e;
        int e1 = (e0 == 0) ? 1 : 0;
        #pragma unroll
        for (int e = 0; e < NEXP; e++) if (e != e0 && p[e] > p[e1]) e1 = e;
        float w0 = p[e0], w1 = p[e1];
        float wi = 1.f / (w0 + w1);
        w0 *= wi; w1 *= wi;
        g_tok_e[t * 2 + 0] = e0; g_tok_e[t * 2 + 1] = e1;
        g_tok_w[t * 2 + 0] = w0; g_tok_w[t * 2 + 1] = w1;
        g_zloss[t] = z;
        atomicAdd(&g_counts[e0], 1);
        atomicAdd(&g_counts[e1], 1);
    }
}

// ---------------------------------------------------------------------------
// Single-block setup: offsets, tile descriptors, aux loss scalar.
__global__ __launch_bounds__(256)
void k_setup(float* __restrict__ d_out, int out_size) {
    __shared__ float red[256];
    int tid = threadIdx.x;
    float s = 0.f;
    for (int t = tid; t < T_TOK; t += 256) s += g_zloss[t];
    red[tid] = s;
    __syncthreads();
    for (int o = 128; o > 0; o >>= 1) {
        if (tid < o) red[tid] += red[tid + o];
        __syncthreads();
    }
    if (tid == 0) {
        int off = 0;
        for (int e = 0; e < NEXP; e++) { g_offsets[e] = off; off += g_counts[e]; }
        g_offsets[NEXP] = off;   // == 8192

        int nt = 0;
        for (int e = 0; e < NEXP; e++) {
            int o0 = g_offsets[e], n = g_counts[e];
            for (int i = 0; i * BM < n; i++) {
                g_tile_expert[nt] = e;
                g_tile_row0[nt]   = o0 + i * BM;
                g_tile_rows[nt]   = min(BM, n - i * BM);
                nt++;
            }
        }
        for (int i = 0; i < T_TOK / BM; i++) {
            g_tile_expert[nt] = NEXP;       // shared expert marker
            g_tile_row0[nt]   = SHARED_OFF + i * BM;
            g_tile_rows[nt]   = BM;
            nt++;
        }
        g_num_tiles = nt;

        // aux loss
        float zl  = red[0] / (float)T_TOK;
        float tot = (float)(T_TOK * 2 + T_TOK);           // 12288
        float ideal = 1.f / (float)(NEXP + 1);
        float lb = 0.f;
        for (int e = 0; e < NEXP; e++) {
            float d = (float)g_counts[e] / tot - ideal;
            lb += d * d;
        }
        {
            float d = (float)T_TOK / tot - ideal;
            lb += d * d;
        }
        lb /= (float)(NEXP + 1);
        if (out_size > T_TOK * HID)
            d_out[out_size - 1] = 0.01f * lb + 0.01f * zl;
    }
}

// ---------------------------------------------------------------------------
// Scatter tokens into expert-sorted slots.
__global__ void k_scatter() {
    int t = blockIdx.x * 256 + threadIdx.x;
    if (t >= T_TOK) return;
    #pragma unroll
    for (int k = 0; k < 2; k++) {
        int e = g_tok_e[t * 2 + k];
        int pos = atomicAdd(&g_cursor[e], 1);
        int slot = g_offsets[e] + pos;
        g_perm_token[slot]  = t;
        g_perm_weight[slot] = g_tok_w[t * 2 + k];
        g_slot_of[t * 3 + k] = slot;
    }
    int slot = SHARED_OFF + t;
    g_perm_token[slot]  = t;
    g_perm_weight[slot] = 1.0f;   // 1/SHARED
    g_slot_of[t * 3 + 2] = slot;
}

// ---------------------------------------------------------------------------
// Pass 1: act = silu(X @ gate^T) * (X @ up^T), gathered rows, per-expert tiles.
__global__ __launch_bounds__(256, 2)
void k_pass1(const float* __restrict__ x,
             const float* __restrict__ gate_w,
             const float* __restrict__ up_w,
             const float* __restrict__ sh_gate,
             const float* __restrict__ sh_up)
{
    int tile = blockIdx.x;
    if (tile >= g_num_tiles) return;
    int e     = g_tile_expert[tile];
    int row0  = g_tile_row0[tile];
    int nrows = g_tile_rows[tile];
    int n0    = blockIdx.y * BN;

    const float* Wg = (e < NEXP) ? gate_w + (size_t)e * INTER * HID : sh_gate;
    const float* Wu = (e < NEXP) ? up_w   + (size_t)e * INTER * HID : sh_up;

    __shared__ float As[BK][BM + 1];
    __shared__ float Bg[BK][BN + 1];
    __shared__ float Bu[BK][BN + 1];
    __shared__ const float* Arow[BM];

    int tid = threadIdx.x;
    if (tid < BM) {
        int lr = (tid < nrows) ? tid : 0;
        Arow[tid] = x + (size_t)g_perm_token[row0 + lr] * HID;
    }
    __syncthreads();

    int l_row = tid >> 2;              // 0..63
    int l_k   = (tid & 3) << 2;        // 0,4,8,12
    const float* ap  = Arow[l_row] + l_k;
    const float* bgp = Wg + (size_t)(n0 + l_row) * HID + l_k;
    const float* bup = Wu + (size_t)(n0 + l_row) * HID + l_k;

    int ty = tid >> 4, tx = tid & 15;
    int m0 = ty << 2, c0 = tx << 2;

    float ag[4][4] = {{0.f}}, au[4][4] = {{0.f}};

    for (int k0 = 0; k0 < HID; k0 += BK) {
        float4 av = *(const float4*)(ap + k0);
        float4 gv = *(const float4*)(bgp + k0);
        float4 uv = *(const float4*)(bup + k0);
        __syncthreads();
        As[l_k + 0][l_row] = av.x; As[l_k + 1][l_row] = av.y;
        As[l_k + 2][l_row] = av.z; As[l_k + 3][l_row] = av.w;
        Bg[l_k + 0][l_row] = gv.x; Bg[l_k + 1][l_row] = gv.y;
        Bg[l_k + 2][l_row] = gv.z; Bg[l_k + 3][l_row] = gv.w;
        Bu[l_k + 0][l_row] = uv.x; Bu[l_k + 1][l_row] = uv.y;
        Bu[l_k + 2][l_row] = uv.z; Bu[l_k + 3][l_row] = uv.w;
        __syncthreads();
        #pragma unroll
        for (int k = 0; k < BK; k++) {
            float a[4], bgr[4], bur[4];
            #pragma unroll
            for (int i = 0; i < 4; i++) a[i] = As[k][m0 + i];
            #pragma unroll
            for (int j = 0; j < 4; j++) { bgr[j] = Bg[k][c0 + j]; bur[j] = Bu[k][c0 + j]; }
            #pragma unroll
            for (int i = 0; i < 4; i++) {
                #pragma unroll
                for (int j = 0; j < 4; j++) {
                    ag[i][j] += a[i] * bgr[j];
                    au[i][j] += a[i] * bur[j];
                }
            }
        }
    }

    #pragma unroll
    for (int i = 0; i < 4; i++) {
        int lr = m0 + i;
        if (lr < nrows) {
            float* dst = g_act + (size_t)(row0 + lr) * INTER + n0 + c0;
            #pragma unroll
            for (int j = 0; j < 4; j++) {
                float g = ag[i][j];
                float sig = __fdividef(1.0f, 1.0f + __expf(-g));
                dst[j] = g * sig * au[i][j];
            }
        }
    }
}

// ---------------------------------------------------------------------------
// Pass 2: y = (act @ down^T) * weight  (weight folded into epilogue)
__global__ __launch_bounds__(256, 2)
void k_pass2(const float* __restrict__ down_w,
             const float* __restrict__ sh_down)
{
    int tile = blockIdx.x;
    if (tile >= g_num_tiles) return;
    int e     = g_tile_expert[tile];
    int row0  = g_tile_row0[tile];
    int nrows = g_tile_rows[tile];
    int n0    = blockIdx.y * BN;

    const float* Wd = (e < NEXP) ? down_w + (size_t)e * HID * INTER : sh_down;

    __shared__ float As[BK][BM + 1];
    __shared__ float Bs[BK][BN + 1];

    int tid = threadIdx.x;
    int l_row = tid >> 2;
    int l_k   = (tid & 3) << 2;
    int arow  = (l_row < nrows) ? l_row : 0;
    const float* ap = g_act + (size_t)(row0 + arow) * INTER + l_k;
    const float* bp = Wd + (size_t)(n0 + l_row) * INTER + l_k;

    int ty = tid >> 4, tx = tid & 15;
    int m0 = ty << 2, c0 = tx << 2;

    float acc[4][4] = {{0.f}};

    for (int k0 = 0; k0 < INTER; k0 += BK) {
        float4 av = *(const float4*)(ap + k0);
        float4 bv = *(const float4*)(bp + k0);
        __syncthreads();
        As[l_k + 0][l_row] = av.x; As[l_k + 1][l_row] = av.y;
        As[l_k + 2][l_row] = av.z; As[l_k + 3][l_row] = av.w;
        Bs[l_k + 0][l_row] = bv.x; Bs[l_k + 1][l_row] = bv.y;
        Bs[l_k + 2][l_row] = bv.z; Bs[l_k + 3][l_row] = bv.w;
        __syncthreads();
        #pragma unroll
        for (int k = 0; k < BK; k++) {
            float a[4], b[4];
            #pragma unroll
            for (int i = 0; i < 4; i++) a[i] = As[k][m0 + i];
            #pragma unroll
            for (int j = 0; j < 4; j++) b[j] = Bs[k][c0 + j];
            #pragma unroll
            for (int i = 0; i < 4; i++) {
                #pragma unroll
                for (int j = 0; j < 4; j++) acc[i][j] += a[i] * b[j];
            }
        }
    }

    #pragma unroll
    for (int i = 0; i < 4; i++) {
        int lr = m0 + i;
        if (lr < nrows) {
            float w = g_perm_weight[row0 + lr];
            float* dst = g_y + (size_t)(row0 + lr) * HID + n0 + c0;
            #pragma unroll
            for (int j = 0; j < 4; j++) dst[j] = acc[i][j] * w;
        }
    }
}

// ---------------------------------------------------------------------------
// Combine: out[t] = y[routed0] + y[routed1] + y[shared]
__global__ void k_combine(float* __restrict__ out) {
    int idx = blockIdx.x * 256 + threadIdx.x;    // over T*H/4
    int t = idx >> 8;                            // HID/4 = 256 float4 per token
    int j = (idx & 255) << 2;
    int s0 = g_slot_of[t * 3 + 0];
    int s1 = g_slot_of[t * 3 + 1];
    int s2 = g_slot_of[t * 3 + 2];
    float4 a = *(const float4*)(g_y + (size_t)s0 * HID + j);
    float4 b = *(const float4*)(g_y + (size_t)s1 * HID + j);
    float4 c = *(const float4*)(g_y + (size_t)s2 * HID + j);
    float4 o;
    o.x = a.x + b.x + c.x;
    o.y = a.y + b.y + c.y;
    o.z = a.z + b.z + c.z;
    o.w = a.w + b.w + c.w;
    *(float4*)(out + (size_t)t * HID + j) = o;
}

// ---------------------------------------------------------------------------
extern "C" void kernel_launch(void* const* d_in, const int* in_sizes, int n_in,
                              void* d_out, int out_size) {
    const float* x  = (const float*)d_in[0];   // hidden_states [2,2048,1024]
    const float* rw = (const float*)d_in[1];   // router_w [8,1024]
    const float* gw = (const float*)d_in[2];   // gate_w [8,4096,1024]
    const float* uw = (const float*)d_in[3];   // up_w [8,4096,1024]
    const float* dw = (const float*)d_in[4];   // down_w [8,1024,4096]
    const float* sg = (const float*)d_in[5];   // sh_gate_w [4096,1024]
    const float* su = (const float*)d_in[6];   // sh_up_w [4096,1024]
    const float* sd = (const float*)d_in[7];   // sh_down_w [1024,4096]
    float* out = (float*)d_out;

    k_zero<<<1, 32>>>();
    k_router<<<T_TOK / 8, 256>>>(x, rw);
    k_setup<<<1, 256>>>(out, out_size);
    k_scatter<<<T_TOK / 256, 256>>>();

    dim3 g1(MAX_TILES, INTER / BN);   // (224, 64)
    k_pass1<<<g1, 256>>>(x, gw, uw, sg, su);

    dim3 g2(MAX_TILES, HID / BN);     // (224, 16)
    k_pass2<<<g2, 256>>>(dw, sd);

    k_combine<<<(T_TOK * HID / 4) / 256, 256>>>(out);
}

// round 10
// speedup vs baseline: 3.0658x; 3.0658x over previous
#include <cuda_runtime.h>
#include <cuda_bf16.h>
#include <math.h>

// Problem constants
#define T_TOK 4096
#define HID   1024
#define INTER 4096
#define NEXP  8
#define NSLOT 12288          // T*K routed + T shared
#define SHARED_OFF 8192      // T*K
#define MAX_TILES 112        // sum ceil(n_e/128) (<=71) + 32 shared tiles

#define BM 128
#define BN 64
#define BK 32
#define LDSM_LD 40           // smem row stride (bf16): 32 + 8 pad -> conflict-free ldmatrix

// ---- device-global scratch (no allocations allowed) ----
__device__ __nv_bfloat162 g_act[(size_t)NSLOT * INTER];  // swiglu act as (hi,lo) bf16 pair
__device__ float g_y[(size_t)NSLOT * HID];
__device__ int   g_perm_token[NSLOT];
__device__ float g_perm_weight[NSLOT];
__device__ int   g_slot_of[T_TOK * 3];
__device__ int   g_counts[NEXP];
__device__ int   g_offsets[NEXP + 1];
__device__ int   g_cursor[NEXP];
__device__ float g_zloss[T_TOK];
__device__ int   g_tok_e[T_TOK * 2];
__device__ float g_tok_w[T_TOK * 2];
__device__ int   g_tile_expert[MAX_TILES];
__device__ int   g_tile_row0[MAX_TILES];
__device__ int   g_tile_rows[MAX_TILES];
__device__ int   g_num_tiles;

// ---------------------------------------------------------------------------
// MMA / ldmatrix helpers
// ---------------------------------------------------------------------------
__device__ __forceinline__ unsigned su32(const void* p) {
    return (unsigned)__cvta_generic_to_shared(p);
}

__device__ __forceinline__ void ldsm4(unsigned r[4], unsigned addr) {
    asm volatile("ldmatrix.sync.aligned.m8n8.x4.shared.b16 {%0,%1,%2,%3}, [%4];\n"
                 : "=r"(r[0]), "=r"(r[1]), "=r"(r[2]), "=r"(r[3]) : "r"(addr));
}

__device__ __forceinline__ void mma16816(float c[4], const unsigned a[4], const unsigned b[2]) {
    asm volatile(
        "mma.sync.aligned.m16n8k16.row.col.f32.bf16.bf16.f32 "
        "{%0,%1,%2,%3}, {%4,%5,%6,%7}, {%8,%9}, {%0,%1,%2,%3};\n"
        : "+f"(c[0]), "+f"(c[1]), "+f"(c[2]), "+f"(c[3])
        : "r"(a[0]), "r"(a[1]), "r"(a[2]), "r"(a[3]), "r"(b[0]), "r"(b[1]));
}

// Split 8 consecutive f32 (k-contiguous) into packed bf16x2 hi / lo uint4's.
__device__ __forceinline__ void split8(float4 a, float4 b, uint4& hi, uint4& lo) {
    float f[8] = {a.x, a.y, a.z, a.w, b.x, b.y, b.z, b.w};
    unsigned h[4], l[4];
    #pragma unroll
    for (int i = 0; i < 4; i++) {
        float f0 = f[2 * i], f1 = f[2 * i + 1];
        __nv_bfloat16 h0 = __float2bfloat16(f0);
        __nv_bfloat16 h1 = __float2bfloat16(f1);
        float r0 = f0 - __bfloat162float(h0);
        float r1 = f1 - __bfloat162float(h1);
        __nv_bfloat162 hp = __nv_bfloat162(h0, h1);
        __nv_bfloat162 lp = __nv_bfloat162(__float2bfloat16(r0), __float2bfloat16(r1));
        h[i] = *reinterpret_cast<unsigned*>(&hp);
        l[i] = *reinterpret_cast<unsigned*>(&lp);
    }
    hi = make_uint4(h[0], h[1], h[2], h[3]);
    lo = make_uint4(l[0], l[1], l[2], l[3]);
}

// Pack one f32 into (hi, lo) bf16x2 bit pattern.
__device__ __forceinline__ unsigned pack_split(float x) {
    __nv_bfloat16 h = __float2bfloat16(x);
    __nv_bfloat16 l = __float2bfloat16(x - __bfloat162float(h));
    __nv_bfloat162 v(h, l);
    return *reinterpret_cast<unsigned*>(&v);
}

// ---------------------------------------------------------------------------
__global__ void k_zero() {
    int i = threadIdx.x;
    if (i < NEXP) { g_counts[i] = 0; g_cursor[i] = 0; }
}

// ---------------------------------------------------------------------------
// Router: one warp per token.
__global__ __launch_bounds__(256)
void k_router(const float* __restrict__ x, const float* __restrict__ rw) {
    __shared__ float s_rw[NEXP * HID];
    for (int i = threadIdx.x; i < NEXP * HID; i += 256) s_rw[i] = rw[i];
    __syncthreads();

    int warp = threadIdx.x >> 5, lane = threadIdx.x & 31;
    int t = blockIdx.x * 8 + warp;
    const float* xr = x + (size_t)t * HID;

    float acc[NEXP];
    #pragma unroll
    for (int e = 0; e < NEXP; e++) acc[e] = 0.f;
    for (int k = lane; k < HID; k += 32) {
        float xv = xr[k];
        #pragma unroll
        for (int e = 0; e < NEXP; e++) acc[e] += xv * s_rw[e * HID + k];
    }
    #pragma unroll
    for (int e = 0; e < NEXP; e++) {
        #pragma unroll
        for (int o = 16; o > 0; o >>= 1)
            acc[e] += __shfl_xor_sync(0xffffffffu, acc[e], o);
    }
    if (lane == 0) {
        float m = acc[0];
        #pragma unroll
        for (int e = 1; e < NEXP; e++) m = fmaxf(m, acc[e]);
        float p[NEXP], s = 0.f, z = 0.f;
        #pragma unroll
        for (int e = 0; e < NEXP; e++) {
            z += acc[e] * acc[e];
            p[e] = expf(acc[e] - m);
            s += p[e];
        }
        float inv = 1.f / s;
        #pragma unroll
        for (int e = 0; e < NEXP; e++) p[e] *= inv;
        int e0 = 0;
        #pragma unroll
        for (int e = 1; e < NEXP; e++) if (p[e] > p[e0]) e0 = e;
        int e1 = (e0 == 0) ? 1 : 0;
        #pragma unroll
        for (int e = 0; e < NEXP; e++) if (e != e0 && p[e] > p[e1]) e1 = e;
        float w0 = p[e0], w1 = p[e1];
        float wi = 1.f / (w0 + w1);
        w0 *= wi; w1 *= wi;
        g_tok_e[t * 2 + 0] = e0; g_tok_e[t * 2 + 1] = e1;
        g_tok_w[t * 2 + 0] = w0; g_tok_w[t * 2 + 1] = w1;
        g_zloss[t] = z;
        atomicAdd(&g_counts[e0], 1);
        atomicAdd(&g_counts[e1], 1);
    }
}

// ---------------------------------------------------------------------------
// Single-block setup: offsets, tile descriptors, aux loss scalar.
__global__ __launch_bounds__(256)
void k_setup(float* __restrict__ d_out, int out_size) {
    __shared__ float red[256];
    int tid = threadIdx.x;
    float s = 0.f;
    for (int t = tid; t < T_TOK; t += 256) s += g_zloss[t];
    red[tid] = s;
    __syncthreads();
    for (int o = 128; o > 0; o >>= 1) {
        if (tid < o) red[tid] += red[tid + o];
        __syncthreads();
    }
    if (tid == 0) {
        int off = 0;
        for (int e = 0; e < NEXP; e++) { g_offsets[e] = off; off += g_counts[e]; }
        g_offsets[NEXP] = off;

        int nt = 0;
        for (int e = 0; e < NEXP; e++) {
            int o0 = g_offsets[e], n = g_counts[e];
            for (int i = 0; i * BM < n; i++) {
                g_tile_expert[nt] = e;
                g_tile_row0[nt]   = o0 + i * BM;
                g_tile_rows[nt]   = min(BM, n - i * BM);
                nt++;
            }
        }
        for (int i = 0; i < T_TOK / BM; i++) {
            g_tile_expert[nt] = NEXP;
            g_tile_row0[nt]   = SHARED_OFF + i * BM;
            g_tile_rows[nt]   = BM;
            nt++;
        }
        g_num_tiles = nt;

        float zl  = red[0] / (float)T_TOK;
        float tot = (float)(T_TOK * 2 + T_TOK);
        float ideal = 1.f / (float)(NEXP + 1);
        float lb = 0.f;
        for (int e = 0; e < NEXP; e++) {
            float d = (float)g_counts[e] / tot - ideal;
            lb += d * d;
        }
        {
            float d = (float)T_TOK / tot - ideal;
            lb += d * d;
        }
        lb /= (float)(NEXP + 1);
        if (out_size > T_TOK * HID)
            d_out[out_size - 1] = 0.01f * lb + 0.01f * zl;
    }
}

// ---------------------------------------------------------------------------
__global__ void k_scatter() {
    int t = blockIdx.x * 256 + threadIdx.x;
    if (t >= T_TOK) return;
    #pragma unroll
    for (int k = 0; k < 2; k++) {
        int e = g_tok_e[t * 2 + k];
        int pos = atomicAdd(&g_cursor[e], 1);
        int slot = g_offsets[e] + pos;
        g_perm_token[slot]  = t;
        g_perm_weight[slot] = g_tok_w[t * 2 + k];
        g_slot_of[t * 3 + k] = slot;
    }
    int slot = SHARED_OFF + t;
    g_perm_token[slot]  = t;
    g_perm_weight[slot] = 1.0f;
    g_slot_of[t * 3 + 2] = slot;
}

// ---------------------------------------------------------------------------
// Pass 1: act = silu(X @ gate^T) * (X @ up^T), bf16-split tensor core GEMM.
// Output stored as packed (hi,lo) bf16x2 per element.
__global__ __launch_bounds__(256, 1)
void k_pass1(const float* __restrict__ x,
             const float* __restrict__ gate_w,
             const float* __restrict__ up_w,
             const float* __restrict__ sh_gate,
             const float* __restrict__ sh_up)
{
    int tile = blockIdx.x;
    if (tile >= g_num_tiles) return;
    int e     = g_tile_expert[tile];
    int row0  = g_tile_row0[tile];
    int nrows = g_tile_rows[tile];
    int n0    = blockIdx.y * BN;

    const float* Wg = (e < NEXP) ? gate_w + (size_t)e * INTER * HID : sh_gate;
    const float* Wu = (e < NEXP) ? up_w   + (size_t)e * INTER * HID : sh_up;

    __shared__ __align__(16) __nv_bfloat16 sA[2][BM][LDSM_LD];
    __shared__ __align__(16) __nv_bfloat16 sBg[2][BN][LDSM_LD];
    __shared__ __align__(16) __nv_bfloat16 sBu[2][BN][LDSM_LD];
    __shared__ const float* Arow[BM];

    int tid = threadIdx.x;
    if (tid < BM) {
        int lr = (tid < nrows) ? tid : 0;
        Arow[tid] = x + (size_t)g_perm_token[row0 + lr] * HID;
    }
    __syncthreads();

    // global load mapping
    int arow = tid >> 1, aks = (tid & 1) * 16;
    const float* apb = Arow[arow] + aks;
    int brow = tid >> 2, bks = (tid & 3) * 8;
    const float* gp = Wg + (size_t)(n0 + brow) * HID + bks;
    const float* up = Wu + (size_t)(n0 + brow) * HID + bks;

    int lane = tid & 31, warp = tid >> 5;
    int wm = warp >> 1, wn = warp & 1;

    float accg[2][4][4], accu[2][4][4];
    #pragma unroll
    for (int i = 0; i < 2; i++)
        #pragma unroll
        for (int j = 0; j < 4; j++)
            #pragma unroll
            for (int q = 0; q < 4; q++) { accg[i][j][q] = 0.f; accu[i][j][q] = 0.f; }

    float4 aR[4], gR[2], uR[2];
    #pragma unroll
    for (int i = 0; i < 4; i++) aR[i] = *(const float4*)(apb + i * 4);
    gR[0] = *(const float4*)(gp);     gR[1] = *(const float4*)(gp + 4);
    uR[0] = *(const float4*)(up);     uR[1] = *(const float4*)(up + 4);

    // precompute ldmatrix source offsets (constant across chunks except kb)
    int a_r = (lane & 15), a_k = (lane >> 4) * 8;
    int b_r = ((lane >> 4) << 3) + (lane & 7), b_k = ((lane >> 3) & 1) * 8;

    for (int c = 0; c < HID / BK; c++) {
        __syncthreads();
        {
            uint4 h, l;
            split8(aR[0], aR[1], h, l);
            *(uint4*)&sA[0][arow][aks] = h;  *(uint4*)&sA[1][arow][aks] = l;
            split8(aR[2], aR[3], h, l);
            *(uint4*)&sA[0][arow][aks + 8] = h;  *(uint4*)&sA[1][arow][aks + 8] = l;
            split8(gR[0], gR[1], h, l);
            *(uint4*)&sBg[0][brow][bks] = h; *(uint4*)&sBg[1][brow][bks] = l;
            split8(uR[0], uR[1], h, l);
            *(uint4*)&sBu[0][brow][bks] = h; *(uint4*)&sBu[1][brow][bks] = l;
        }
        __syncthreads();
        if (c + 1 < HID / BK) {
            int k0 = (c + 1) * BK;
            #pragma unroll
            for (int i = 0; i < 4; i++) aR[i] = *(const float4*)(apb + k0 + i * 4);
            gR[0] = *(const float4*)(gp + k0); gR[1] = *(const float4*)(gp + k0 + 4);
            uR[0] = *(const float4*)(up + k0); uR[1] = *(const float4*)(up + k0 + 4);
        }
        #pragma unroll
        for (int kk = 0; kk < 2; kk++) {
            int kb = kk * 16;
            unsigned ah[2][4], al[2][4];
            #pragma unroll
            for (int mi = 0; mi < 2; mi++) {
                int r = wm * 32 + mi * 16 + a_r;
                ldsm4(ah[mi], su32(&sA[0][r][kb + a_k]));
                ldsm4(al[mi], su32(&sA[1][r][kb + a_k]));
            }
            #pragma unroll
            for (int p = 0; p < 2; p++) {
                int bn = wn * 32 + p * 16 + b_r;
                int bk = kb + b_k;
                unsigned bh[4], bl[4];
                ldsm4(bh, su32(&sBg[0][bn][bk]));
                ldsm4(bl, su32(&sBg[1][bn][bk]));
                #pragma unroll
                for (int mi = 0; mi < 2; mi++)
                    #pragma unroll
                    for (int q = 0; q < 2; q++) {
                        float* cg = accg[mi][2 * p + q];
                        mma16816(cg, ah[mi], &bh[2 * q]);
                        mma16816(cg, ah[mi], &bl[2 * q]);
                        mma16816(cg, al[mi], &bh[2 * q]);
                    }
                ldsm4(bh, su32(&sBu[0][bn][bk]));
                ldsm4(bl, su32(&sBu[1][bn][bk]));
                #pragma unroll
                for (int mi = 0; mi < 2; mi++)
                    #pragma unroll
                    for (int q = 0; q < 2; q++) {
                        float* cu = accu[mi][2 * p + q];
                        mma16816(cu, ah[mi], &bh[2 * q]);
                        mma16816(cu, ah[mi], &bl[2 * q]);
                        mma16816(cu, al[mi], &bh[2 * q]);
                    }
            }
        }
    }

    // epilogue: silu(g)*u, split-pack, store
    int r0l = wm * 32 + (lane >> 2);
    int cb  = wn * 32 + (lane & 3) * 2;
    #pragma unroll
    for (int mi = 0; mi < 2; mi++)
        #pragma unroll
        for (int nt = 0; nt < 4; nt++)
            #pragma unroll
            for (int h = 0; h < 2; h++) {
                int lr = r0l + mi * 16 + h * 8;
                if (lr < nrows) {
                    int col = cb + nt * 8;
                    float g0 = accg[mi][nt][2 * h], g1 = accg[mi][nt][2 * h + 1];
                    float u0 = accu[mi][nt][2 * h], u1 = accu[mi][nt][2 * h + 1];
                    float a0 = g0 * __fdividef(1.f, 1.f + __expf(-g0)) * u0;
                    float a1 = g1 * __fdividef(1.f, 1.f + __expf(-g1)) * u1;
                    uint2 v = make_uint2(pack_split(a0), pack_split(a1));
                    *(uint2*)(g_act + (size_t)(row0 + lr) * INTER + n0 + col) = v;
                }
            }
}

// ---------------------------------------------------------------------------
// Pass 2: y = (act @ down^T) * weight, act already (hi,lo)-packed.
__global__ __launch_bounds__(256, 1)
void k_pass2(const float* __restrict__ down_w,
             const float* __restrict__ sh_down)
{
    int tile = blockIdx.x;
    if (tile >= g_num_tiles) return;
    int e     = g_tile_expert[tile];
    int row0  = g_tile_row0[tile];
    int nrows = g_tile_rows[tile];
    int n0    = blockIdx.y * BN;

    const float* Wd = (e < NEXP) ? down_w + (size_t)e * HID * INTER : sh_down;

    __shared__ __align__(16) __nv_bfloat16 sA[2][BM][LDSM_LD];
    __shared__ __align__(16) __nv_bfloat16 sB[2][BN][LDSM_LD];

    int tid = threadIdx.x;
    int arow = tid >> 1, aks = (tid & 1) * 16;
    int ar = (arow < nrows) ? arow : 0;
    const unsigned* apb = (const unsigned*)(g_act + (size_t)(row0 + ar) * INTER + aks);
    int brow = tid >> 2, bks = (tid & 3) * 8;
    const float* bp = Wd + (size_t)(n0 + brow) * INTER + bks;

    int lane = tid & 31, warp = tid >> 5;
    int wm = warp >> 1, wn = warp & 1;

    float acc[2][4][4];
    #pragma unroll
    for (int i = 0; i < 2; i++)
        #pragma unroll
        for (int j = 0; j < 4; j++)
            #pragma unroll
            for (int q = 0; q < 4; q++) acc[i][j][q] = 0.f;

    uint4 aR[4];
    float4 bR[2];
    #pragma unroll
    for (int i = 0; i < 4; i++) aR[i] = *(const uint4*)(apb + i * 4);
    bR[0] = *(const float4*)(bp);  bR[1] = *(const float4*)(bp + 4);

    int a_r = (lane & 15), a_k = (lane >> 4) * 8;
    int b_r = ((lane >> 4) << 3) + (lane & 7), b_k = ((lane >> 3) & 1) * 8;

    for (int c = 0; c < INTER / BK; c++) {
        __syncthreads();
        {
            // unpack (hi,lo) pairs -> separate hi/lo k-packed pairs via byte_perm
            #pragma unroll
            for (int seg = 0; seg < 2; seg++) {
                unsigned u[8] = {aR[2*seg].x, aR[2*seg].y, aR[2*seg].z, aR[2*seg].w,
                                 aR[2*seg+1].x, aR[2*seg+1].y, aR[2*seg+1].z, aR[2*seg+1].w};
                uint4 h, l;
                h.x = __byte_perm(u[0], u[1], 0x5410); l.x = __byte_perm(u[0], u[1], 0x7632);
                h.y = __byte_perm(u[2], u[3], 0x5410); l.y = __byte_perm(u[2], u[3], 0x7632);
                h.z = __byte_perm(u[4], u[5], 0x5410); l.z = __byte_perm(u[4], u[5], 0x7632);
                h.w = __byte_perm(u[6], u[7], 0x5410); l.w = __byte_perm(u[6], u[7], 0x7632);
                *(uint4*)&sA[0][arow][aks + seg * 8] = h;
                *(uint4*)&sA[1][arow][aks + seg * 8] = l;
            }
            uint4 h, l;
            split8(bR[0], bR[1], h, l);
            *(uint4*)&sB[0][brow][bks] = h; *(uint4*)&sB[1][brow][bks] = l;
        }
        __syncthreads();
        if (c + 1 < INTER / BK) {
            int k0 = (c + 1) * BK;
            #pragma unroll
            for (int i = 0; i < 4; i++) aR[i] = *(const uint4*)(apb + k0 + i * 4);
            bR[0] = *(const float4*)(bp + k0); bR[1] = *(const float4*)(bp + k0 + 4);
        }
        #pragma unroll
        for (int kk = 0; kk < 2; kk++) {
            int kb = kk * 16;
            unsigned ah[2][4], al[2][4];
            #pragma unroll
            for (int mi = 0; mi < 2; mi++) {
                int r = wm * 32 + mi * 16 + a_r;
                ldsm4(ah[mi], su32(&sA[0][r][kb + a_k]));
                ldsm4(al[mi], su32(&sA[1][r][kb + a_k]));
            }
            #pragma unroll
            for (int p = 0; p < 2; p++) {
                int bn = wn * 32 + p * 16 + b_r;
                int bk = kb + b_k;
                unsigned bh[4], bl[4];
                ldsm4(bh, su32(&sB[0][bn][bk]));
                ldsm4(bl, su32(&sB[1][bn][bk]));
                #pragma unroll
                for (int mi = 0; mi < 2; mi++)
                    #pragma unroll
                    for (int q = 0; q < 2; q++) {
                        float* cc = acc[mi][2 * p + q];
                        mma16816(cc, ah[mi], &bh[2 * q]);
                        mma16816(cc, ah[mi], &bl[2 * q]);
                        mma16816(cc, al[mi], &bh[2 * q]);
                    }
            }
        }
    }

    int r0l = wm * 32 + (lane >> 2);
    int cb  = wn * 32 + (lane & 3) * 2;
    #pragma unroll
    for (int mi = 0; mi < 2; mi++)
        #pragma unroll
        for (int nt = 0; nt < 4; nt++)
            #pragma unroll
            for (int h = 0; h < 2; h++) {
                int lr = r0l + mi * 16 + h * 8;
                if (lr < nrows) {
                    float w = g_perm_weight[row0 + lr];
                    int col = cb + nt * 8;
                    float2 v = make_float2(acc[mi][nt][2 * h] * w,
                                           acc[mi][nt][2 * h + 1] * w);
                    *(float2*)(g_y + (size_t)(row0 + lr) * HID + n0 + col) = v;
                }
            }
}

// ---------------------------------------------------------------------------
__global__ void k_combine(float* __restrict__ out) {
    int idx = blockIdx.x * 256 + threadIdx.x;
    int t = idx >> 8;
    int j = (idx & 255) << 2;
    int s0 = g_slot_of[t * 3 + 0];
    int s1 = g_slot_of[t * 3 + 1];
    int s2 = g_slot_of[t * 3 + 2];
    float4 a = *(const float4*)(g_y + (size_t)s0 * HID + j);
    float4 b = *(const float4*)(g_y + (size_t)s1 * HID + j);
    float4 c = *(const float4*)(g_y + (size_t)s2 * HID + j);
    float4 o;
    o.x = a.x + b.x + c.x;
    o.y = a.y + b.y + c.y;
    o.z = a.z + b.z + c.z;
    o.w = a.w + b.w + c.w;
    *(float4*)(out + (size_t)t * HID + j) = o;
}

// ---------------------------------------------------------------------------
extern "C" void kernel_launch(void* const* d_in, const int* in_sizes, int n_in,
                              void* d_out, int out_size) {
    const float* x  = (const float*)d_in[0];
    const float* rw = (const float*)d_in[1];
    const float* gw = (const float*)d_in[2];
    const float* uw = (const float*)d_in[3];
    const float* dw = (const float*)d_in[4];
    const float* sg = (const float*)d_in[5];
    const float* su = (const float*)d_in[6];
    const float* sd = (const float*)d_in[7];
    float* out = (float*)d_out;

    k_zero<<<1, 32>>>();
    k_router<<<T_TOK / 8, 256>>>(x, rw);
    k_setup<<<1, 256>>>(out, out_size);
    k_scatter<<<T_TOK / 256, 256>>>();

    dim3 g1(MAX_TILES, INTER / BN);   // (112, 64)
    k_pass1<<<g1, 256>>>(x, gw, uw, sg, su);

    dim3 g2(MAX_TILES, HID / BN);     // (112, 16)
    k_pass2<<<g2, 256>>>(dw, sd);

    k_combine<<<(T_TOK * HID / 4) / 256, 256>>>(out);
}